// round 13
// baseline (speedup 1.0000x reference)
#include <cuda_runtime.h>
#include <cstdint>

// Problem constants
static constexpr int N_ = 1024;
static constexpr int K_ = 32;
static constexpr int I_ = 10000;
static constexpr int I4_ = I_ / 4;       // 2500 float4 chunks per row

static constexpr float CS_  = 0.43280850f;     // 3/(10*ln2)
// CB3 = 51.2+25.6+12.7 (magic-number rebase + exp-bias consts)
//     + 0.0528766 (-0.1*log2(ln2)) + 0.1135508 (poly H0)
static constexpr float CB3_ = 89.6664274f;

// Precomputed per-(k,i) score base: sc = CS*logits + CB3  (1.28 MB, L2-resident)
__device__ float g_sc[K_ * I_];

__device__ __forceinline__ float lg2_approx(float v) {
    float r; asm("lg2.approx.f32 %0, %1;" : "=f"(r) : "f"(v)); return r;
}
__device__ __forceinline__ float ex2_approx(float v) {
    float r; asm("ex2.approx.f32 %0, %1;" : "=f"(r) : "f"(v)); return r;
}
// f32x2 packed helpers (sm_103a FFMA2 path — ptxas never emits these from C++)
__device__ __forceinline__ uint64_t pk(float lo, float hi) {
    uint64_t r; asm("mov.b64 %0, {%1, %2};" : "=l"(r) : "f"(lo), "f"(hi)); return r;
}
__device__ __forceinline__ void upk(uint64_t v, float& lo, float& hi) {
    asm("mov.b64 {%0, %1}, %2;" : "=f"(lo), "=f"(hi) : "l"(v));
}
__device__ __forceinline__ uint64_t fma2(uint64_t a, uint64_t b, uint64_t c) {
    uint64_t d; asm("fma.rn.f32x2 %0, %1, %2, %3;" : "=l"(d) : "l"(a), "l"(b), "l"(c)); return d;
}
__device__ __forceinline__ uint64_t add2(uint64_t a, uint64_t b) {
    uint64_t d; asm("add.rn.f32x2 %0, %1, %2;" : "=l"(d) : "l"(a), "l"(b)); return d;
}

__global__ void precompute_sc_kernel(const float* __restrict__ logits) {
    int i = blockIdx.x * blockDim.x + threadIdx.x;
    if (i < (K_ * I_) / 4) {
        float4 v = reinterpret_cast<const float4*>(logits)[i];
        v.x = fmaf(v.x, CS_, CB3_);
        v.y = fmaf(v.y, CS_, CB3_);
        v.z = fmaf(v.z, CS_, CB3_);
        v.w = fmaf(v.w, CS_, CB3_);
        reinterpret_cast<float4*>(g_sc)[i] = v;
    }
}

// out[n,k] = (sum_i x*w) / (sum_i w),   w = 2^score,
// score = sc - 0.1*log2(-ln u) (sc holds logits term + every additive const).
//
// With L = lg2(u) (<0), b = bits(L): the exponent part of the score comes
// from the magic-number float view f = uint_as_float((b>>9)|0x4B000000)
// = 2^23 + b/512 exactly, folded into sc by one scalar FFMA (R12 showed the
// IMAD.HI variant is slightly slower; SHF+LOP3 stays). Mantissa correction
// -0.1*(log2 m - (m-1)) is a degree-3 poly evaluated as SCALAR per-lane
// FFMAs with literal/cbank constants: same issue count as the packed form,
// shorter critical path (no cross-lane convergence before ex2), and frees
// the 6 registers of packed coefficient splats. IMNMX.U32 clamp on b
// (-L >= 2^-27) guards lg2.approx underflow at u->1 (m==1 there, poly=0).
//
// Memory: u prefetched in registers at distance THREE (3 float4 buffers,
// ~1200 warp-cycles of latency cover — the freed poly registers pay for the
// third stage); sc (L2-resident) at distance two. The 78 iterations run as
// a statically unrolled 6-phase schedule (LCM(3,2)): 12x6 main + 6-body
// epilogue with tapering refills, zero buffer-rotation moves.
// Layout: mode-W, 1 CTA x 1024 threads/SM (multi-CTA suffers L1tex spread;
// cp.async staging is slower — commit/wait serializes, R11).
__global__ void __launch_bounds__(1024, 1)
concrete_selector_kernel(const float* __restrict__ x,
                         const float* __restrict__ u,
                         float* __restrict__ out) {
    __shared__ __align__(16) float xs[I_];   // x row for this n (40000 B)

    const int n   = blockIdx.x;
    const int tid = threadIdx.x;

    // Cooperative load of x[n, :] into shared (float4)
    {
        const float4* __restrict__ xg4 =
            reinterpret_cast<const float4*>(x + (size_t)n * I_);
        float4* xs4 = reinterpret_cast<float4*>(xs);
        for (int i = tid; i < I4_; i += 1024) xs4[i] = xg4[i];
    }
    __syncthreads();

    const int warp = tid >> 5;
    const int lane = tid & 31;
    const int k    = warp;    // 32 warps == 32 k's

    const float4* __restrict__ ug4 =
        reinterpret_cast<const float4*>(u + ((size_t)n * K_ + k) * (size_t)I_);
    const float4* __restrict__ cg4 =
        reinterpret_cast<const float4*>(g_sc + (size_t)k * I_);
    const ulonglong2* __restrict__ xsv =
        reinterpret_cast<const ulonglong2*>(xs);   // LDS.128 -> two packed pairs

    uint64_t accA2 = 0;   // packed pair of partial sums of x*w
    uint64_t accB2 = 0;   // packed pair of partial sums of w

    auto ppair = [&](float u0, float u1, float sc0, float sc1, uint64_t xp) {
        float L0 = lg2_approx(u0);                 // XU (u<1 -> L<0)
        float L1 = lg2_approx(u1);
        unsigned b0 = __float_as_uint(L0);
        unsigned b1 = __float_as_uint(L1);
        b0 = b0 > 0xB2000000u ? b0 : 0xB2000000u;  // IMNMX.U32: -L >= 2^-27
        b1 = b1 > 0xB2000000u ? b1 : 0xB2000000u;
        float m0 = __int_as_float((b0 & 0x007fffffu) | 0x3f800000u);  // LOP3
        float m1 = __int_as_float((b1 & 0x007fffffu) | 0x3f800000u);
        float f0 = __uint_as_float((b0 >> 9) | 0x4B000000u);  // SHF+LOP3
        float f1 = __uint_as_float((b1 >> 9) | 0x4B000000u);
        float sv0 = fmaf(f0, -6.1035156e-6f, sc0); // exponent term + score base
        float sv1 = fmaf(f1, -6.1035156e-6f, sc1);
        // deg-3 mantissa poly, scalar Horner (literal/cbank constants)
        float r0 = fmaf(m0, -1.52368e-2f, 1.025445e-1f);
        float r1 = fmaf(m1, -1.52368e-2f, 1.025445e-1f);
        r0 = fmaf(m0, r0, -2.009419e-1f);
        r1 = fmaf(m1, r1, -2.009419e-1f);
        float s0 = fmaf(m0, r0, sv0);              // full log2-score
        float s1 = fmaf(m1, r1, sv1);
        uint64_t wp = pk(ex2_approx(s0), ex2_approx(s1));   // XU x2
        accB2 = add2(accB2, wp);
        accA2 = fma2(xp, wp, accA2);
    };

    // Prologue: u depth-3, sc depth-2
    float4 U[3], S[2];
    U[0] = __ldcs(&ug4[lane]);
    U[1] = __ldcs(&ug4[lane + 32]);
    U[2] = __ldcs(&ug4[lane + 64]);
    S[0] = cg4[lane];
    S[1] = cg4[lane + 32];

    int j = lane;
    // Main: 12 macro-iterations x 6 phases = iterations 0..71
    for (int mit = 0; mit < 12; ++mit) {
        #pragma unroll
        for (int ph = 0; ph < 6; ++ph) {
            float4& Ub = U[ph % 3];
            float4& Sb = S[ph % 2];
            ulonglong2 X = xsv[j];
            ppair(Ub.x, Ub.y, Sb.x, Sb.y, X.x);
            ppair(Ub.z, Ub.w, Sb.z, Sb.w, X.y);
            Ub = __ldcs(&ug4[j + 96]);   // refill for iteration it+3
            Sb = cg4[j + 64];            // refill for iteration it+2
            j += 32;
        }
    }
    // Epilogue: iterations 72..77 with tapering refills (all in-bounds)
    #pragma unroll
    for (int ph = 0; ph < 6; ++ph) {
        float4& Ub = U[ph % 3];
        float4& Sb = S[ph % 2];
        ulonglong2 X = xsv[j];
        ppair(Ub.x, Ub.y, Sb.x, Sb.y, X.x);
        ppair(Ub.z, Ub.w, Sb.z, Sb.w, X.y);
        if (ph < 3) Ub = __ldcs(&ug4[j + 96]);   // feeds iterations 75..77
        if (ph < 4) Sb = cg4[j + 64];            // feeds iterations 74..77
        j += 32;
    }
    // Tail: chunks 2496..2499 handled by lanes 0..3
    if (lane < I4_ - 2496) {
        int jt = 2496 + lane;
        float4 uu = __ldcs(&ug4[jt]);
        float4 cc = cg4[jt];
        ulonglong2 X = xsv[jt];
        ppair(uu.x, uu.y, cc.x, cc.y, X.x);
        ppair(uu.z, uu.w, cc.z, cc.w, X.y);
    }

    // Collapse packed accumulators, then warp reduction
    float a0, a1, bb0, bb1;
    upk(accA2, a0, a1);
    upk(accB2, bb0, bb1);
    float accA = a0 + a1;
    float accB = bb0 + bb1;
    #pragma unroll
    for (int off = 16; off > 0; off >>= 1) {
        accA += __shfl_down_sync(0xffffffffu, accA, off);
        accB += __shfl_down_sync(0xffffffffu, accB, off);
    }
    if (lane == 0) {
        out[(size_t)n * K_ + k] = accA / accB;
    }
}

extern "C" void kernel_launch(void* const* d_in, const int* in_sizes, int n_in,
                              void* d_out, int out_size) {
    const float* x      = (const float*)d_in[0];   // (1024, 10000)
    const float* u      = (const float*)d_in[1];   // (1024, 32, 10000)
    const float* logits = (const float*)d_in[2];   // (32, 10000)
    float* out = (float*)d_out;                    // (1024, 32)
    (void)in_sizes; (void)n_in; (void)out_size;

    // Stage 1: fold logits scaling + all additive constants into g_sc
    precompute_sc_kernel<<<(K_ * I_ / 4 + 255) / 256, 256>>>(logits);
    // Stage 2: main reduction
    concrete_selector_kernel<<<N_, 1024>>>(x, u, out);
}